// round 15
// baseline (speedup 1.0000x reference)
#include <cuda_runtime.h>
#include <cuda_fp16.h>
#include <math.h>
#include <stdint.h>

// Problem constants
#define S_TOK 4096
#define DIM   1024
#define NEXP  8
#define HID   4096
#define NSCORES (NEXP * S_TOK)

#define TK_BLOCKS 64

// ---------------- device scratch ----------------
__device__ float g_scores[NSCORES];
__device__ int   g_cnt[NEXP];
__device__ int   g_rows[NEXP * S_TOK];
__device__ float g_w[NEXP * S_TOK];
__device__ int   g_pos[NSCORES];
__device__ __half g_hidden[(size_t)NEXP * S_TOK * HID];   // fp16, k-pair packed
__device__ float g_y[(size_t)NEXP * S_TOK * DIM];
// fused top-k state
__device__ int      g_hist4[4][256];
__device__ volatile unsigned g_prefixv;
__device__ volatile int      g_kkv;
__device__ int      g_bar_arrive;
__device__ volatile int g_bar_release;

// ---------------- router (exact fp32, x staged via smem) ----------------
__global__ void router_kernel(const float* __restrict__ x,
                              const float* __restrict__ gw,
                              const float* __restrict__ eb) {
    int s = blockIdx.x;
    int warp = threadIdx.x >> 5, lane = threadIdx.x & 31;
    __shared__ float xsh[DIM];
    {
        int i4 = threadIdx.x * 4;
        *(float4*)&xsh[i4] = *(const float4*)(x + (size_t)s * DIM + i4);
    }
    __syncthreads();
    const float* g = gw + (size_t)warp * DIM;
    float acc = 0.f;
    for (int i = lane; i < DIM; i += 32) acc += xsh[i] * g[i];
    #pragma unroll
    for (int o = 16; o; o >>= 1) acc += __shfl_xor_sync(0xFFFFFFFFu, acc, o);
    __shared__ float l[NEXP];
    if (lane == 0) l[warp] = acc + eb[warp];
    __syncthreads();
    if (threadIdx.x < NEXP) {
        float m = l[0];
        #pragma unroll
        for (int e = 1; e < NEXP; e++) m = fmaxf(m, l[e]);
        float sum = 0.f;
        #pragma unroll
        for (int e = 0; e < NEXP; e++) sum += expf(l[e] - m);
        g_scores[threadIdx.x * S_TOK + s] = expf(l[threadIdx.x] - m) / sum;
    }
}

// ---------------- init: zero all fused-topk state (per replay) --------------
__global__ void topk_init_kernel(const int* __restrict__ cap) {
    int t = blockIdx.x * blockDim.x + threadIdx.x;
    if (t < 1024) ((int*)g_hist4)[t] = 0;
    if (t < NEXP) g_cnt[t] = 0;
    if (t == 0) {
        int k = S_TOK * cap[0];
        if (k < 1) k = 1;
        if (k > NSCORES) k = NSCORES;
        g_kkv = k;
        g_prefixv = 0u;
        g_bar_arrive = 0;
        g_bar_release = 0;
    }
}

// software grid barrier: all TK_BLOCKS CTAs are resident (64 < 148 SMs)
__device__ __forceinline__ void grid_bar(int target) {
    __syncthreads();
    if (threadIdx.x == 0) {
        __threadfence();
        int t = atomicAdd(&g_bar_arrive, 1);
        if (t == TK_BLOCKS - 1) {
            g_bar_arrive = 0;
            __threadfence();
            g_bar_release = target;
        } else {
            while (g_bar_release < target) { }
        }
        __threadfence();
    }
    __syncthreads();
}

// ---------------- fused exact top-k radix select + build --------------------
__global__ __launch_bounds__(256)
void topk_build_kernel() {
    int tid = threadIdx.x;
    int phase = 0;
    __shared__ int hist[256];
    __shared__ int sfx[256];

    #pragma unroll
    for (int pass = 0; pass < 4; pass++) {
        int shift = 24 - pass * 8;
        unsigned mask = (pass == 0) ? 0u : (0xFFFFFFFFu << (32 - 8 * pass));
        unsigned prefix = g_prefixv;

        hist[tid] = 0;
        __syncthreads();
        for (int i = blockIdx.x * 256 + tid; i < NSCORES; i += TK_BLOCKS * 256) {
            unsigned u = __float_as_uint(g_scores[i]);
            if ((u & mask) == prefix) atomicAdd(&hist[(u >> shift) & 255], 1);
        }
        __syncthreads();
        if (hist[tid]) atomicAdd(&g_hist4[pass][tid], hist[tid]);

        grid_bar(++phase);

        if (blockIdx.x == 0) {
            sfx[tid] = g_hist4[pass][tid];
            __syncthreads();
            // inclusive suffix scan: sfx[t] = sum_{i>=t} hist[i]
            #pragma unroll
            for (int off = 1; off < 256; off <<= 1) {
                int v = (tid + off < 256) ? sfx[tid + off] : 0;
                __syncthreads();
                sfx[tid] += v;
                __syncthreads();
            }
            int kk = g_kkv;
            int Sb = sfx[tid];
            int Sn = (tid == 255) ? 0 : sfx[tid + 1];
            if (Sb >= kk && Sn < kk) {          // unique winner bin
                g_prefixv = prefix | ((unsigned)tid << shift);
                g_kkv = kk - Sn;
            }
            if (tid == 0 && sfx[0] < kk) {      // degenerate fallback: bin 0
                g_kkv = kk - ((255 >= 1) ? sfx[1] : 0);
            }
        }
        grid_bar(++phase);
    }

    // build phase: threshold = k-th largest score (exact)
    float th = __uint_as_float(g_prefixv);
    for (int i = blockIdx.x * 256 + tid; i < NSCORES; i += TK_BLOCKS * 256) {
        float sc = g_scores[i];
        int e = i >> 12;
        int p = -1;
        if (sc >= th) {
            int r = atomicAdd(&g_cnt[e], 1);
            g_rows[e * S_TOK + r] = i & (S_TOK - 1);
            g_w[e * S_TOK + r]    = sc;
            p = r;
        }
        g_pos[i] = p;
    }
}

// ---------------- fp16 tensor-core GEMM (m16n8k16, smem double-buffered) ----
// (exact R10 configuration — empirically fastest)
#define BM 128
#define BN 128
#define BK 16
#define ASTRW 12      // As row stride in b32 words (8 data + 4 pad)
#define BSTRW 136     // Bs row stride in b32 words
#define A_WORDS (BM * ASTRW)
#define B_WORDS (8 * BSTRW)

__device__ __forceinline__ void mma_f16(float* c, const unsigned* a, const unsigned* b) {
    asm volatile("mma.sync.aligned.m16n8k16.row.col.f32.f16.f16.f32 "
        "{%0,%1,%2,%3}, {%4,%5,%6,%7}, {%8,%9}, {%0,%1,%2,%3};"
        : "+f"(c[0]), "+f"(c[1]), "+f"(c[2]), "+f"(c[3])
        : "r"(a[0]), "r"(a[1]), "r"(a[2]), "r"(a[3]), "r"(b[0]), "r"(b[1]));
}
__device__ __forceinline__ unsigned pack2(float lo, float hi) {
    __half2 h = __floats2half2_rn(lo, hi);
    return *reinterpret_cast<unsigned*>(&h);
}

__device__ __forceinline__ void compute_bk16(const unsigned* As, const unsigned* Bs,
                                             int wm, int wn, int gid, int tig,
                                             float acc[4][4][4]) {
    unsigned af[4][4], bf[4][2];
    #pragma unroll
    for (int mt = 0; mt < 4; mt++) {
        int r = wm + mt * 16 + gid;
        af[mt][0] = As[r * ASTRW + tig];
        af[mt][1] = As[(r + 8) * ASTRW + tig];
        af[mt][2] = As[r * ASTRW + tig + 4];
        af[mt][3] = As[(r + 8) * ASTRW + tig + 4];
    }
    #pragma unroll
    for (int nt = 0; nt < 4; nt++) {
        int n = wn + nt * 8 + gid;
        bf[nt][0] = Bs[tig * BSTRW + n];
        bf[nt][1] = Bs[(tig + 4) * BSTRW + n];
    }
    #pragma unroll
    for (int mt = 0; mt < 4; mt++)
        #pragma unroll
        for (int nt = 0; nt < 4; nt++)
            mma_f16(acc[mt][nt], af[mt], bf[nt]);
}

// GEMM1: g_hidden[e][r][h] = gelu( x[tok[r]] @ w1[e] + b1[e] ),  K=DIM
__global__ __launch_bounds__(256, 2)
void gemm1_kernel(const float* __restrict__ x,
                  const float* __restrict__ w1,
                  const float* __restrict__ b1) {
    int e = blockIdx.z;
    int n = g_cnt[e];
    int row0 = blockIdx.y * BM;
    if (row0 >= n) return;
    int col0 = blockIdx.x * BN;
    const float* Bg = w1 + (size_t)e * DIM * HID;
    const int ldb = HID;
    const int KIT = DIM / BK;

    __shared__ __align__(16) unsigned As[2][A_WORDS];
    __shared__ __align__(16) unsigned Bs[2][B_WORDS];
    __shared__ int toks[BM];

    int tid = threadIdx.x;
    if (tid < BM) {
        int mg = row0 + tid;
        if (mg >= n) mg = n - 1;
        toks[tid] = g_rows[e * S_TOK + mg];
    }
    __syncthreads();

    int lane = tid & 31, warp = tid >> 5;
    int gid = lane >> 2, tig = lane & 3;
    int wm = (warp & 1) * 64, wn = (warp >> 1) * 32;

    float acc[4][4][4];
    #pragma unroll
    for (int mt = 0; mt < 4; mt++)
        #pragma unroll
        for (int nt = 0; nt < 4; nt++)
            #pragma unroll
            for (int i = 0; i < 4; i++) acc[mt][nt][i] = 0.f;

    int aR = tid >> 1, grp = tid & 1;
    const float* aSrc = x + (size_t)toks[aR] * DIM + grp * 8;
    int kp = warp, bn0 = lane * 4;
    const float* bSrcE = Bg + (size_t)(2 * kp) * ldb + col0 + bn0;
    const float* bSrcO = bSrcE + ldb;
    unsigned aOff = aR * ASTRW + grp * 4;
    unsigned bOff = kp * BSTRW + bn0;

    float ra[8];
    float4 rbE, rbO;
    *(float4*)&ra[0] = *(const float4*)aSrc;
    *(float4*)&ra[4] = *(const float4*)(aSrc + 4);
    rbE = *(const float4*)bSrcE;
    rbO = *(const float4*)bSrcO;
    {
        uint4 aw;
        aw.x = pack2(ra[0], ra[1]); aw.y = pack2(ra[2], ra[3]);
        aw.z = pack2(ra[4], ra[5]); aw.w = pack2(ra[6], ra[7]);
        *(uint4*)&As[0][aOff] = aw;
        uint4 bw;
        bw.x = pack2(rbE.x, rbO.x); bw.y = pack2(rbE.y, rbO.y);
        bw.z = pack2(rbE.z, rbO.z); bw.w = pack2(rbE.w, rbO.w);
        *(uint4*)&Bs[0][bOff] = bw;
    }
    __syncthreads();
    *(float4*)&ra[0] = *(const float4*)(aSrc + BK);
    *(float4*)&ra[4] = *(const float4*)(aSrc + BK + 4);
    rbE = *(const float4*)(bSrcE + (size_t)BK * ldb);
    rbO = *(const float4*)(bSrcO + (size_t)BK * ldb);

    for (int it = 0; it < KIT; it++) {
        int cur = it & 1;
        if (it + 1 < KIT) {
            uint4 aw;
            aw.x = pack2(ra[0], ra[1]); aw.y = pack2(ra[2], ra[3]);
            aw.z = pack2(ra[4], ra[5]); aw.w = pack2(ra[6], ra[7]);
            *(uint4*)&As[cur ^ 1][aOff] = aw;
            uint4 bw;
            bw.x = pack2(rbE.x, rbO.x); bw.y = pack2(rbE.y, rbO.y);
            bw.z = pack2(rbE.z, rbO.z); bw.w = pack2(rbE.w, rbO.w);
            *(uint4*)&Bs[cur ^ 1][bOff] = bw;
        }
        if (it + 2 < KIT) {
            int k0 = (it + 2) * BK;
            *(float4*)&ra[0] = *(const float4*)(aSrc + k0);
            *(float4*)&ra[4] = *(const float4*)(aSrc + k0 + 4);
            rbE = *(const float4*)(bSrcE + (size_t)k0 * ldb);
            rbO = *(const float4*)(bSrcO + (size_t)k0 * ldb);
        }
        compute_bk16(As[cur], Bs[cur], wm, wn, gid, tig, acc);
        __syncthreads();
    }

    const float* b1e = b1 + (size_t)e * HID;
    __half* Hb = g_hidden + (size_t)e * S_TOK * HID;
    #pragma unroll
    for (int mt = 0; mt < 4; mt++) {
        #pragma unroll
        for (int half = 0; half < 2; half++) {
            int r = row0 + wm + mt * 16 + gid + half * 8;
            if (r >= n) continue;
            #pragma unroll
            for (int nt = 0; nt < 4; nt++) {
                int c = col0 + wn + nt * 8 + 2 * tig;
                float v0 = acc[mt][nt][half * 2 + 0] + b1e[c];
                float v1 = acc[mt][nt][half * 2 + 1] + b1e[c + 1];
                float t0 = tanhf(0.7978845608028654f * (v0 + 0.044715f * v0 * v0 * v0));
                float t1 = tanhf(0.7978845608028654f * (v1 + 0.044715f * v1 * v1 * v1));
                float g0 = 0.5f * v0 * (1.0f + t0);
                float g1 = 0.5f * v1 * (1.0f + t1);
                *(unsigned*)&Hb[(size_t)r * HID + c] = pack2(g0, g1);
            }
        }
    }
}

// GEMM2: g_y[e][r][d] = g_w[r] * ( g_hidden[e][r] @ w2[e] + b2[e] ),  K=HID
__global__ __launch_bounds__(256, 2)
void gemm2_kernel(const float* __restrict__ w2,
                  const float* __restrict__ b2) {
    int e = blockIdx.z;
    int n = g_cnt[e];
    int row0 = blockIdx.y * BM;
    if (row0 >= n) return;
    int col0 = blockIdx.x * BN;
    const __half* Ag = g_hidden + (size_t)e * S_TOK * HID;
    const float* Bg = w2 + (size_t)e * HID * DIM;
    const int ldb = DIM;
    const int KIT = HID / BK;

    __shared__ __align__(16) unsigned As[2][A_WORDS];
    __shared__ __align__(16) unsigned Bs[2][B_WORDS];

    int tid = threadIdx.x;
    int lane = tid & 31, warp = tid >> 5;
    int gid = lane >> 2, tig = lane & 3;
    int wm = (warp & 1) * 64, wn = (warp >> 1) * 32;

    float acc[4][4][4];
    #pragma unroll
    for (int mt = 0; mt < 4; mt++)
        #pragma unroll
        for (int nt = 0; nt < 4; nt++)
            #pragma unroll
            for (int i = 0; i < 4; i++) acc[mt][nt][i] = 0.f;

    int aR = tid >> 1, grp = tid & 1;
    int mg = row0 + aR; if (mg >= n) mg = n - 1;
    const __half* aSrc = Ag + (size_t)mg * HID + grp * 8;   // fp16 k-pairs
    int kp = warp, bn0 = lane * 4;
    const float* bSrcE = Bg + (size_t)(2 * kp) * ldb + col0 + bn0;
    const float* bSrcO = bSrcE + ldb;
    unsigned aOff = aR * ASTRW + grp * 4;
    unsigned bOff = kp * BSTRW + bn0;

    uint4 ra;
    float4 rbE, rbO;
    ra = *(const uint4*)aSrc;
    rbE = *(const float4*)bSrcE;
    rbO = *(const float4*)bSrcO;
    {
        *(uint4*)&As[0][aOff] = ra;
        uint4 bw;
        bw.x = pack2(rbE.x, rbO.x); bw.y = pack2(rbE.y, rbO.y);
        bw.z = pack2(rbE.z, rbO.z); bw.w = pack2(rbE.w, rbO.w);
        *(uint4*)&Bs[0][bOff] = bw;
    }
    __syncthreads();
    ra = *(const uint4*)(aSrc + BK);
    rbE = *(const float4*)(bSrcE + (size_t)BK * ldb);
    rbO = *(const float4*)(bSrcO + (size_t)BK * ldb);

    for (int it = 0; it < KIT; it++) {
        int cur = it & 1;
        if (it + 1 < KIT) {
            *(uint4*)&As[cur ^ 1][aOff] = ra;
            uint4 bw;
            bw.x = pack2(rbE.x, rbO.x); bw.y = pack2(rbE.y, rbO.y);
            bw.z = pack2(rbE.z, rbO.z); bw.w = pack2(rbE.w, rbO.w);
            *(uint4*)&Bs[cur ^ 1][bOff] = bw;
        }
        if (it + 2 < KIT) {
            int k0 = (it + 2) * BK;
            ra = *(const uint4*)(aSrc + k0);
            rbE = *(const float4*)(bSrcE + (size_t)k0 * ldb);
            rbO = *(const float4*)(bSrcO + (size_t)k0 * ldb);
        }
        compute_bk16(As[cur], Bs[cur], wm, wn, gid, tig, acc);
        __syncthreads();
    }

    const float* b2e = b2 + (size_t)e * DIM;
    #pragma unroll
    for (int mt = 0; mt < 4; mt++) {
        #pragma unroll
        for (int half = 0; half < 2; half++) {
            int r = row0 + wm + mt * 16 + gid + half * 8;
            if (r >= n) continue;
            float wg = g_w[e * S_TOK + r];
            #pragma unroll
            for (int nt = 0; nt < 4; nt++) {
                int c = col0 + wn + nt * 8 + 2 * tig;
                float2 o;
                o.x = wg * (acc[mt][nt][half * 2 + 0] + b2e[c]);
                o.y = wg * (acc[mt][nt][half * 2 + 1] + b2e[c + 1]);
                *(float2*)&g_y[((size_t)e * S_TOK + r) * DIM + c] = o;
            }
        }
    }
}

// ---------------- deterministic combine (1 block/token, float4) -------------
__global__ void combine_kernel(float* __restrict__ out) {
    int s = blockIdx.x;
    __shared__ int pos[NEXP];
    if (threadIdx.x < NEXP) pos[threadIdx.x] = g_pos[threadIdx.x * S_TOK + s];
    __syncthreads();
    int d = threadIdx.x * 4;
    float4 acc = make_float4(0.f, 0.f, 0.f, 0.f);
    #pragma unroll
    for (int e = 0; e < NEXP; e++) {
        int p = pos[e];
        if (p >= 0) {
            float4 v = *(const float4*)&g_y[((size_t)(e * S_TOK + p)) * DIM + d];
            acc.x += v.x; acc.y += v.y; acc.z += v.z; acc.w += v.w;
        }
    }
    *(float4*)&out[(size_t)s * DIM + d] = acc;
}

// ---------------- launch ----------------
extern "C" void kernel_launch(void* const* d_in, const int* in_sizes, int n_in,
                              void* d_out, int out_size) {
    const float* x  = (const float*)d_in[0];
    const float* gw = (const float*)d_in[1];
    const float* eb = (const float*)d_in[2];
    const float* w1 = (const float*)d_in[3];
    const float* b1 = (const float*)d_in[4];
    const float* w2 = (const float*)d_in[5];
    const float* b2 = (const float*)d_in[6];
    const int*  cap = (const int*)d_in[7];
    float* out = (float*)d_out;

    router_kernel<<<S_TOK, 256>>>(x, gw, eb);
    topk_init_kernel<<<4, 256>>>(cap);
    topk_build_kernel<<<TK_BLOCKS, 256>>>();
    gemm1_kernel<<<dim3(HID / BN, S_TOK / BM, NEXP), 256>>>(x, w1, b1);
    gemm2_kernel<<<dim3(DIM / BN, S_TOK / BM, NEXP), 256>>>(w2, b2);
    combine_kernel<<<S_TOK, 256>>>(out);
}

// round 16
// speedup vs baseline: 1.5740x; 1.5740x over previous
#include <cuda_runtime.h>
#include <cuda_fp16.h>
#include <math.h>
#include <stdint.h>

// Problem constants
#define S_TOK 4096
#define DIM   1024
#define NEXP  8
#define HID   4096
#define NSCORES (NEXP * S_TOK)

// ---------------- device scratch ----------------
__device__ float g_scores[NSCORES];
__device__ float g_thresh;
__device__ int   g_cnt[NEXP];
__device__ int   g_rows[NEXP * S_TOK];
__device__ float g_w[NEXP * S_TOK];
__device__ int   g_pos[NSCORES];
__device__ __half g_hidden[(size_t)NEXP * S_TOK * HID];   // fp16, k-pair packed
__device__ float g_y[(size_t)NEXP * S_TOK * DIM];
// parallel top-k state
__device__ int      g_hist4[4][256];
__device__ unsigned g_prefix;
__device__ int      g_kk;

// ---------------- router (exact fp32, x staged via smem) --------------------
// block 0 additionally initializes top-k state (consumed only by later kernels)
__global__ void router_kernel(const float* __restrict__ x,
                              const float* __restrict__ gw,
                              const float* __restrict__ eb,
                              const int* __restrict__ cap) {
    int s = blockIdx.x;
    int warp = threadIdx.x >> 5, lane = threadIdx.x & 31;
    __shared__ float xsh[DIM];
    if (blockIdx.x == 0) {
        int t = threadIdx.x;
        for (int i = t; i < 1024; i += 256) ((int*)g_hist4)[i] = 0;
        if (t < NEXP) g_cnt[t] = 0;
        if (t == 0) {
            int k = S_TOK * cap[0];
            if (k < 1) k = 1;
            if (k > NSCORES) k = NSCORES;
            g_kk = k;
            g_prefix = 0u;
        }
    }
    {
        int i4 = threadIdx.x * 4;
        *(float4*)&xsh[i4] = *(const float4*)(x + (size_t)s * DIM + i4);
    }
    __syncthreads();
    const float* g = gw + (size_t)warp * DIM;
    float acc = 0.f;
    for (int i = lane; i < DIM; i += 32) acc += xsh[i] * g[i];
    #pragma unroll
    for (int o = 16; o; o >>= 1) acc += __shfl_xor_sync(0xFFFFFFFFu, acc, o);
    __shared__ float l[NEXP];
    if (lane == 0) l[warp] = acc + eb[warp];
    __syncthreads();
    if (threadIdx.x < NEXP) {
        float m = l[0];
        #pragma unroll
        for (int e = 1; e < NEXP; e++) m = fmaxf(m, l[e]);
        float sum = 0.f;
        #pragma unroll
        for (int e = 0; e < NEXP; e++) sum += expf(l[e] - m);
        g_scores[threadIdx.x * S_TOK + s] = expf(l[threadIdx.x] - m) / sum;
    }
}

// ---------------- parallel exact top-k threshold (radix select) -------------
__global__ void topk_scan_kernel(int pass) {
    int shift = 24 - pass * 8;
    unsigned mask = (pass == 0) ? 0u : (0xFFFFFFFFu << (32 - 8 * pass));
    unsigned prefix = g_prefix;
    __shared__ int hist[256];
    for (int i = threadIdx.x; i < 256; i += blockDim.x) hist[i] = 0;
    __syncthreads();
    for (int i = blockIdx.x * blockDim.x + threadIdx.x; i < NSCORES;
         i += gridDim.x * blockDim.x) {
        unsigned u = __float_as_uint(g_scores[i]);
        if ((u & mask) == prefix) atomicAdd(&hist[(u >> shift) & 255], 1);
    }
    __syncthreads();
    for (int i = threadIdx.x; i < 256; i += blockDim.x)
        if (hist[i]) atomicAdd(&g_hist4[pass][i], hist[i]);
}

// parallel reduce: 256 threads, suffix-scan in smem, unique winner bin
__global__ void topk_reduce_kernel(int pass) {
    int tid = threadIdx.x;
    __shared__ int sfx[256];
    sfx[tid] = g_hist4[pass][tid];
    __syncthreads();
    #pragma unroll
    for (int off = 1; off < 256; off <<= 1) {
        int v = (tid + off < 256) ? sfx[tid + off] : 0;
        __syncthreads();
        sfx[tid] += v;
        __syncthreads();
    }
    int shift = 24 - pass * 8;
    int kk = g_kk;
    int Sb = sfx[tid];
    int Sn = (tid == 255) ? 0 : sfx[tid + 1];
    if (Sb >= kk && Sn < kk) {        // unique winner: S[b] >= kk > S[b+1]
        unsigned np = g_prefix | ((unsigned)tid << shift);
        g_prefix = np;
        g_kk = kk - Sn;
        if (pass == 3) g_thresh = __uint_as_float(np);
    }
    // degenerate case (all counts below kk): bin 0 wins
    if (tid == 0 && sfx[0] < kk) {
        g_kk = kk - sfx[1];
        if (pass == 3) g_thresh = __uint_as_float(g_prefix);
    }
}

__global__ void build_kernel() {
    int i = blockIdx.x * blockDim.x + threadIdx.x;
    if (i >= NSCORES) return;
    float sc = g_scores[i];
    int e = i >> 12;
    int p = -1;
    if (sc >= g_thresh) {
        int r = atomicAdd(&g_cnt[e], 1);
        g_rows[e * S_TOK + r] = i & (S_TOK - 1);
        g_w[e * S_TOK + r]    = sc;
        p = r;
    }
    g_pos[i] = p;
}

// ---------------- fp16 tensor-core GEMM (m16n8k16, smem double-buffered) ----
// (exact R10 configuration — empirically fastest)
#define BM 128
#define BN 128
#define BK 16
#define ASTRW 12      // As row stride in b32 words (8 data + 4 pad)
#define BSTRW 136     // Bs row stride in b32 words
#define A_WORDS (BM * ASTRW)
#define B_WORDS (8 * BSTRW)

__device__ __forceinline__ void mma_f16(float* c, const unsigned* a, const unsigned* b) {
    asm volatile("mma.sync.aligned.m16n8k16.row.col.f32.f16.f16.f32 "
        "{%0,%1,%2,%3}, {%4,%5,%6,%7}, {%8,%9}, {%0,%1,%2,%3};"
        : "+f"(c[0]), "+f"(c[1]), "+f"(c[2]), "+f"(c[3])
        : "r"(a[0]), "r"(a[1]), "r"(a[2]), "r"(a[3]), "r"(b[0]), "r"(b[1]));
}
__device__ __forceinline__ unsigned pack2(float lo, float hi) {
    __half2 h = __floats2half2_rn(lo, hi);
    return *reinterpret_cast<unsigned*>(&h);
}

__device__ __forceinline__ void compute_bk16(const unsigned* As, const unsigned* Bs,
                                             int wm, int wn, int gid, int tig,
                                             float acc[4][4][4]) {
    unsigned af[4][4], bf[4][2];
    #pragma unroll
    for (int mt = 0; mt < 4; mt++) {
        int r = wm + mt * 16 + gid;
        af[mt][0] = As[r * ASTRW + tig];
        af[mt][1] = As[(r + 8) * ASTRW + tig];
        af[mt][2] = As[r * ASTRW + tig + 4];
        af[mt][3] = As[(r + 8) * ASTRW + tig + 4];
    }
    #pragma unroll
    for (int nt = 0; nt < 4; nt++) {
        int n = wn + nt * 8 + gid;
        bf[nt][0] = Bs[tig * BSTRW + n];
        bf[nt][1] = Bs[(tig + 4) * BSTRW + n];
    }
    #pragma unroll
    for (int mt = 0; mt < 4; mt++)
        #pragma unroll
        for (int nt = 0; nt < 4; nt++)
            mma_f16(acc[mt][nt], af[mt], bf[nt]);
}

// GEMM1: g_hidden[e][r][h] = gelu( x[tok[r]] @ w1[e] + b1[e] ),  K=DIM
__global__ __launch_bounds__(256, 2)
void gemm1_kernel(const float* __restrict__ x,
                  const float* __restrict__ w1,
                  const float* __restrict__ b1) {
    int e = blockIdx.z;
    int n = g_cnt[e];
    int row0 = blockIdx.y * BM;
    if (row0 >= n) return;
    int col0 = blockIdx.x * BN;
    const float* Bg = w1 + (size_t)e * DIM * HID;
    const int ldb = HID;
    const int KIT = DIM / BK;

    __shared__ __align__(16) unsigned As[2][A_WORDS];
    __shared__ __align__(16) unsigned Bs[2][B_WORDS];
    __shared__ int toks[BM];

    int tid = threadIdx.x;
    if (tid < BM) {
        int mg = row0 + tid;
        if (mg >= n) mg = n - 1;
        toks[tid] = g_rows[e * S_TOK + mg];
    }
    __syncthreads();

    int lane = tid & 31, warp = tid >> 5;
    int gid = lane >> 2, tig = lane & 3;
    int wm = (warp & 1) * 64, wn = (warp >> 1) * 32;

    float acc[4][4][4];
    #pragma unroll
    for (int mt = 0; mt < 4; mt++)
        #pragma unroll
        for (int nt = 0; nt < 4; nt++)
            #pragma unroll
            for (int i = 0; i < 4; i++) acc[mt][nt][i] = 0.f;

    int aR = tid >> 1, grp = tid & 1;
    const float* aSrc = x + (size_t)toks[aR] * DIM + grp * 8;
    int kp = warp, bn0 = lane * 4;
    const float* bSrcE = Bg + (size_t)(2 * kp) * ldb + col0 + bn0;
    const float* bSrcO = bSrcE + ldb;
    unsigned aOff = aR * ASTRW + grp * 4;
    unsigned bOff = kp * BSTRW + bn0;

    float ra[8];
    float4 rbE, rbO;
    *(float4*)&ra[0] = *(const float4*)aSrc;
    *(float4*)&ra[4] = *(const float4*)(aSrc + 4);
    rbE = *(const float4*)bSrcE;
    rbO = *(const float4*)bSrcO;
    {
        uint4 aw;
        aw.x = pack2(ra[0], ra[1]); aw.y = pack2(ra[2], ra[3]);
        aw.z = pack2(ra[4], ra[5]); aw.w = pack2(ra[6], ra[7]);
        *(uint4*)&As[0][aOff] = aw;
        uint4 bw;
        bw.x = pack2(rbE.x, rbO.x); bw.y = pack2(rbE.y, rbO.y);
        bw.z = pack2(rbE.z, rbO.z); bw.w = pack2(rbE.w, rbO.w);
        *(uint4*)&Bs[0][bOff] = bw;
    }
    __syncthreads();
    *(float4*)&ra[0] = *(const float4*)(aSrc + BK);
    *(float4*)&ra[4] = *(const float4*)(aSrc + BK + 4);
    rbE = *(const float4*)(bSrcE + (size_t)BK * ldb);
    rbO = *(const float4*)(bSrcO + (size_t)BK * ldb);

    for (int it = 0; it < KIT; it++) {
        int cur = it & 1;
        if (it + 1 < KIT) {
            uint4 aw;
            aw.x = pack2(ra[0], ra[1]); aw.y = pack2(ra[2], ra[3]);
            aw.z = pack2(ra[4], ra[5]); aw.w = pack2(ra[6], ra[7]);
            *(uint4*)&As[cur ^ 1][aOff] = aw;
            uint4 bw;
            bw.x = pack2(rbE.x, rbO.x); bw.y = pack2(rbE.y, rbO.y);
            bw.z = pack2(rbE.z, rbO.z); bw.w = pack2(rbE.w, rbO.w);
            *(uint4*)&Bs[cur ^ 1][bOff] = bw;
        }
        if (it + 2 < KIT) {
            int k0 = (it + 2) * BK;
            *(float4*)&ra[0] = *(const float4*)(aSrc + k0);
            *(float4*)&ra[4] = *(const float4*)(aSrc + k0 + 4);
            rbE = *(const float4*)(bSrcE + (size_t)k0 * ldb);
            rbO = *(const float4*)(bSrcO + (size_t)k0 * ldb);
        }
        compute_bk16(As[cur], Bs[cur], wm, wn, gid, tig, acc);
        __syncthreads();
    }

    const float* b1e = b1 + (size_t)e * HID;
    __half* Hb = g_hidden + (size_t)e * S_TOK * HID;
    #pragma unroll
    for (int mt = 0; mt < 4; mt++) {
        #pragma unroll
        for (int half = 0; half < 2; half++) {
            int r = row0 + wm + mt * 16 + gid + half * 8;
            if (r >= n) continue;
            #pragma unroll
            for (int nt = 0; nt < 4; nt++) {
                int c = col0 + wn + nt * 8 + 2 * tig;
                float v0 = acc[mt][nt][half * 2 + 0] + b1e[c];
                float v1 = acc[mt][nt][half * 2 + 1] + b1e[c + 1];
                float t0 = tanhf(0.7978845608028654f * (v0 + 0.044715f * v0 * v0 * v0));
                float t1 = tanhf(0.7978845608028654f * (v1 + 0.044715f * v1 * v1 * v1));
                float g0 = 0.5f * v0 * (1.0f + t0);
                float g1 = 0.5f * v1 * (1.0f + t1);
                *(unsigned*)&Hb[(size_t)r * HID + c] = pack2(g0, g1);
            }
        }
    }
}

// GEMM2: g_y[e][r][d] = g_w[r] * ( g_hidden[e][r] @ w2[e] + b2[e] ),  K=HID
__global__ __launch_bounds__(256, 2)
void gemm2_kernel(const float* __restrict__ w2,
                  const float* __restrict__ b2) {
    int e = blockIdx.z;
    int n = g_cnt[e];
    int row0 = blockIdx.y * BM;
    if (row0 >= n) return;
    int col0 = blockIdx.x * BN;
    const __half* Ag = g_hidden + (size_t)e * S_TOK * HID;
    const float* Bg = w2 + (size_t)e * HID * DIM;
    const int ldb = DIM;
    const int KIT = HID / BK;

    __shared__ __align__(16) unsigned As[2][A_WORDS];
    __shared__ __align__(16) unsigned Bs[2][B_WORDS];

    int tid = threadIdx.x;
    int lane = tid & 31, warp = tid >> 5;
    int gid = lane >> 2, tig = lane & 3;
    int wm = (warp & 1) * 64, wn = (warp >> 1) * 32;

    float acc[4][4][4];
    #pragma unroll
    for (int mt = 0; mt < 4; mt++)
        #pragma unroll
        for (int nt = 0; nt < 4; nt++)
            #pragma unroll
            for (int i = 0; i < 4; i++) acc[mt][nt][i] = 0.f;

    int aR = tid >> 1, grp = tid & 1;
    int mg = row0 + aR; if (mg >= n) mg = n - 1;
    const __half* aSrc = Ag + (size_t)mg * HID + grp * 8;   // fp16 k-pairs
    int kp = warp, bn0 = lane * 4;
    const float* bSrcE = Bg + (size_t)(2 * kp) * ldb + col0 + bn0;
    const float* bSrcO = bSrcE + ldb;
    unsigned aOff = aR * ASTRW + grp * 4;
    unsigned bOff = kp * BSTRW + bn0;

    uint4 ra;
    float4 rbE, rbO;
    ra = *(const uint4*)aSrc;
    rbE = *(const float4*)bSrcE;
    rbO = *(const float4*)bSrcO;
    {
        *(uint4*)&As[0][aOff] = ra;
        uint4 bw;
        bw.x = pack2(rbE.x, rbO.x); bw.y = pack2(rbE.y, rbO.y);
        bw.z = pack2(rbE.z, rbO.z); bw.w = pack2(rbE.w, rbO.w);
        *(uint4*)&Bs[0][bOff] = bw;
    }
    __syncthreads();
    ra = *(const uint4*)(aSrc + BK);
    rbE = *(const float4*)(bSrcE + (size_t)BK * ldb);
    rbO = *(const float4*)(bSrcO + (size_t)BK * ldb);

    for (int it = 0; it < KIT; it++) {
        int cur = it & 1;
        if (it + 1 < KIT) {
            *(uint4*)&As[cur ^ 1][aOff] = ra;
            uint4 bw;
            bw.x = pack2(rbE.x, rbO.x); bw.y = pack2(rbE.y, rbO.y);
            bw.z = pack2(rbE.z, rbO.z); bw.w = pack2(rbE.w, rbO.w);
            *(uint4*)&Bs[cur ^ 1][bOff] = bw;
        }
        if (it + 2 < KIT) {
            int k0 = (it + 2) * BK;
            ra = *(const uint4*)(aSrc + k0);
            rbE = *(const float4*)(bSrcE + (size_t)k0 * ldb);
            rbO = *(const float4*)(bSrcO + (size_t)k0 * ldb);
        }
        compute_bk16(As[cur], Bs[cur], wm, wn, gid, tig, acc);
        __syncthreads();
    }

    const float* b2e = b2 + (size_t)e * DIM;
    #pragma unroll
    for (int mt = 0; mt < 4; mt++) {
        #pragma unroll
        for (int half = 0; half < 2; half++) {
            int r = row0 + wm + mt * 16 + gid + half * 8;
            if (r >= n) continue;
            float wg = g_w[e * S_TOK + r];
            #pragma unroll
            for (int nt = 0; nt < 4; nt++) {
                int c = col0 + wn + nt * 8 + 2 * tig;
                float2 o;
                o.x = wg * (acc[mt][nt][half * 2 + 0] + b2e[c]);
                o.y = wg * (acc[mt][nt][half * 2 + 1] + b2e[c + 1]);
                *(float2*)&g_y[((size_t)e * S_TOK + r) * DIM + c] = o;
            }
        }
    }
}

// ---------------- deterministic combine (1 block/token, float4) -------------
__global__ void combine_kernel(float* __restrict__ out) {
    int s = blockIdx.x;
    __shared__ int pos[NEXP];
    if (threadIdx.x < NEXP) pos[threadIdx.x] = g_pos[threadIdx.x * S_TOK + s];
    __syncthreads();
    int d = threadIdx.x * 4;
    float4 acc = make_float4(0.f, 0.f, 0.f, 0.f);
    #pragma unroll
    for (int e = 0; e < NEXP; e++) {
        int p = pos[e];
        if (p >= 0) {
            float4 v = *(const float4*)&g_y[((size_t)(e * S_TOK + p)) * DIM + d];
            acc.x += v.x; acc.y += v.y; acc.z += v.z; acc.w += v.w;
        }
    }
    *(float4*)&out[(size_t)s * DIM + d] = acc;
}

// ---------------- launch ----------------
extern "C" void kernel_launch(void* const* d_in, const int* in_sizes, int n_in,
                              void* d_out, int out_size) {
    const float* x  = (const float*)d_in[0];
    const float* gw = (const float*)d_in[1];
    const float* eb = (const float*)d_in[2];
    const float* w1 = (const float*)d_in[3];
    const float* b1 = (const float*)d_in[4];
    const float* w2 = (const float*)d_in[5];
    const float* b2 = (const float*)d_in[6];
    const int*  cap = (const int*)d_in[7];
    float* out = (float*)d_out;

    router_kernel<<<S_TOK, 256>>>(x, gw, eb, cap);
    for (int pass = 0; pass < 4; pass++) {
        topk_scan_kernel<<<64, 256>>>(pass);
        topk_reduce_kernel<<<1, 256>>>(pass);
    }
    build_kernel<<<NSCORES / 256, 256>>>();
    gemm1_kernel<<<dim3(HID / BN, S_TOK / BM, NEXP), 256>>>(x, w1, b1);
    gemm2_kernel<<<dim3(DIM / BN, S_TOK / BM, NEXP), 256>>>(w2, b2);
    combine_kernel<<<S_TOK, 256>>>(out);
}